// round 12
// baseline (speedup 1.0000x reference)
#include <cuda_runtime.h>
#include <cuda_fp16.h>
#include <cuda_bf16.h>
#include <math.h>

// Problem dims
#define NCTA   128
#define TPB    512
#define HDIM   1024
#define BSEQ   4096
#define INDIM  512
#define OUTDIM 512

// ---------------- scratch (device globals: allocation-free) ----------------
__device__ float g_g0x[(size_t)BSEQ * 4 * HDIM];   // x@Wih0^T + b0  (64 MB)
__device__ float g_h1all[(size_t)BSEQ * HDIM];     // h1 history    (16 MB)
__device__ float g_h0buf[2][HDIM];
__device__ float g_h1buf[2][HDIM];
__device__ unsigned g_bar_count = 0;
__device__ unsigned g_bar_gen = 0;

// ---------------- grid barrier (sense via monotonically increasing gen) ----
__device__ __forceinline__ void grid_barrier() {
    __threadfence();
    __syncthreads();
    if (threadIdx.x == 0) {
        unsigned gen = *(volatile unsigned*)&g_bar_gen;
        if (atomicAdd(&g_bar_count, 1u) == NCTA - 1u) {
            g_bar_count = 0;
            __threadfence();
            *(volatile unsigned*)&g_bar_gen = gen + 1u;
        } else {
            while (*(volatile unsigned*)&g_bar_gen == gen) { }
        }
        __threadfence();
    }
    __syncthreads();
}

// ---------------- persistent LSTM kernel -----------------------------------
struct __align__(16) LstmSmem {
    half  wts[3][32][HDIM];   // [0]=Whh0 rows, [1]=Whh1 rows, [2]=Wih1 rows (192 KB)
    float h0s[HDIM];
    float h1s[HDIM];
    float red[32];            // gate dot results (layer0 in P, layer1 in Q)
    float vpart[32];          // Whh1 @ h1_prev partial
    float b1row[32];          // bih1+bhh1 for owned rows
    float g0s[32];            // prefetched g0x row slice for this step
    float c0s[8];
    float c1s[8];
};

__device__ __forceinline__ void load_frag(const float* __restrict__ hs, int lane,
                                          float hf[32]) {
#pragma unroll
    for (int i = 0; i < 4; i++) {
        float4 a = *reinterpret_cast<const float4*>(hs + i * 256 + lane * 8);
        float4 b = *reinterpret_cast<const float4*>(hs + i * 256 + lane * 8 + 4);
        hf[i * 8 + 0] = a.x; hf[i * 8 + 1] = a.y; hf[i * 8 + 2] = a.z; hf[i * 8 + 3] = a.w;
        hf[i * 8 + 4] = b.x; hf[i * 8 + 5] = b.y; hf[i * 8 + 6] = b.z; hf[i * 8 + 7] = b.w;
    }
}

// dot of one 1024-wide fp16 weight row with the warp's fp32 h fragment
__device__ __forceinline__ float dot_row(const half* __restrict__ wrow,
                                         const float hf[32], int lane) {
    float a0 = 0.f, a1 = 0.f, a2 = 0.f, a3 = 0.f;
#pragma unroll
    for (int i = 0; i < 4; i++) {
        uint4 wv = *reinterpret_cast<const uint4*>(wrow + i * 256 + lane * 8);
        float2 f0 = __half22float2(*reinterpret_cast<const half2*>(&wv.x));
        float2 f1 = __half22float2(*reinterpret_cast<const half2*>(&wv.y));
        float2 f2 = __half22float2(*reinterpret_cast<const half2*>(&wv.z));
        float2 f3 = __half22float2(*reinterpret_cast<const half2*>(&wv.w));
        a0 = fmaf(f0.x, hf[i * 8 + 0], a0); a1 = fmaf(f0.y, hf[i * 8 + 1], a1);
        a2 = fmaf(f1.x, hf[i * 8 + 2], a2); a3 = fmaf(f1.y, hf[i * 8 + 3], a3);
        a0 = fmaf(f2.x, hf[i * 8 + 4], a0); a1 = fmaf(f2.y, hf[i * 8 + 5], a1);
        a2 = fmaf(f3.x, hf[i * 8 + 6], a2); a3 = fmaf(f3.y, hf[i * 8 + 7], a3);
    }
    float acc = (a0 + a1) + (a2 + a3);
#pragma unroll
    for (int off = 16; off; off >>= 1)
        acc += __shfl_xor_sync(0xffffffffu, acc, off);
    return acc;
}

__device__ __forceinline__ float sigm(float x) { return 1.f / (1.f + __expf(-x)); }

__global__ __launch_bounds__(TPB, 1) void lstm_persist(
    const float* __restrict__ Whh0, const float* __restrict__ Wih1,
    const float* __restrict__ Whh1, const float* __restrict__ bih1,
    const float* __restrict__ bhh1, const float* __restrict__ h0in,
    const float* __restrict__ c0in)
{
    extern __shared__ LstmSmem S_[];
    LstmSmem& S = S_[0];
    const int tid   = threadIdx.x;
    const int lane  = tid & 31;
    const int w     = tid >> 5;        // 0..15
    const int b     = blockIdx.x;      // 0..127
    const int jbase = b * 8;           // owned h indices jbase..jbase+7

    // ---- one-time init: weights -> SMEM fp16, biases, cell state, h bufs ----
    for (int idx = tid; idx < 3 * 32 * HDIM; idx += TPB) {
        int m = idx >> 15;             // 0..2
        int r = (idx >> 10) & 31;
        int k = idx & (HDIM - 1);
        int grow = ((r >> 3) << 10) + jbase + (r & 7);
        const float* W = (m == 0) ? Whh0 : (m == 1 ? Whh1 : Wih1);
        S.wts[m][r][k] = __float2half(W[(size_t)grow * HDIM + k]);
    }
    if (tid < 32) {
        int r = tid;
        int grow = ((r >> 3) << 10) + jbase + (r & 7);
        S.b1row[r] = bih1[grow] + bhh1[grow];
        S.g0s[r]   = g_g0x[grow];                 // prefetch step 0
    }
    if (tid < 8) {
        S.c0s[tid] = c0in[jbase + tid];
        S.c1s[tid] = c0in[HDIM + jbase + tid];
    }
    if (b == 0) {
        for (int k = tid; k < HDIM; k += TPB) {
            __stcg(&g_h0buf[1][k], h0in[k]);
            __stcg(&g_h1buf[1][k], h0in[HDIM + k]);
        }
    }
    grid_barrier();

    for (int t = 0; t < BSEQ; ++t) {
        const int rp = (t + 1) & 1;    // read parity  (prev step's h)
        const int wp = t & 1;          // write parity (this step's h)

        // ================= Phase P =================
        // gates0_t = g0x[t] + Whh0 @ h0_prev;  vpart = Whh1 @ h1_prev
        for (int k = tid; k < HDIM; k += TPB) {
            S.h0s[k] = __ldcg(&g_h0buf[rp][k]);
            S.h1s[k] = __ldcg(&g_h1buf[rp][k]);
        }
        __syncthreads();
        if (w < 8) {
            float hf[32];
            load_frag(S.h0s, lane, hf);
#pragma unroll
            for (int q = 0; q < 4; q++) {
                int r = w + 8 * q;
                float d = dot_row(S.wts[0][r], hf, lane);
                if (lane == 0) S.red[r] = S.g0s[r] + d;
            }
        } else {
            float hf[32];
            load_frag(S.h1s, lane, hf);
#pragma unroll
            for (int q = 0; q < 4; q++) {
                int r = (w - 8) + 8 * q;
                float d = dot_row(S.wts[1][r], hf, lane);
                if (lane == 0) S.vpart[r] = d;
            }
        }
        __syncthreads();
        if (tid < 8) {
            int u = tid;
            float gi = S.red[u], gf = S.red[8 + u], gg = S.red[16 + u], go = S.red[24 + u];
            float c = sigm(gf) * S.c0s[u] + sigm(gi) * tanhf(gg);
            S.c0s[u] = c;
            float h = sigm(go) * tanhf(c);
            __stcg(&g_h0buf[wp][jbase + u], h);
        }
        grid_barrier();

        // ================= Phase Q =================
        // gates1_t = Wih1 @ h0n_t + vpart + b1
        for (int k = tid; k < HDIM; k += TPB)
            S.h0s[k] = __ldcg(&g_h0buf[wp][k]);
        __syncthreads();
        {
            float hf[32];
            load_frag(S.h0s, lane, hf);
#pragma unroll
            for (int q = 0; q < 2; q++) {
                int r = w + 16 * q;
                float d = dot_row(S.wts[2][r], hf, lane);
                if (lane == 0) S.red[r] = d + S.vpart[r] + S.b1row[r];
            }
        }
        // prefetch next step's g0x slice (hides DRAM latency off critical path)
        if (tid >= 64 && tid < 96 && t + 1 < BSEQ) {
            int r = tid - 64;
            int grow = ((r >> 3) << 10) + jbase + (r & 7);
            S.g0s[r] = __ldg(&g_g0x[(size_t)(t + 1) * 4 * HDIM + grow]);
        }
        __syncthreads();
        if (tid < 8) {
            int u = tid;
            float gi = S.red[u], gf = S.red[8 + u], gg = S.red[16 + u], go = S.red[24 + u];
            float c = sigm(gf) * S.c1s[u] + sigm(gi) * tanhf(gg);
            S.c1s[u] = c;
            float h = sigm(go) * tanhf(c);
            __stcg(&g_h1buf[wp][jbase + u], h);
            g_h1all[(size_t)t * HDIM + jbase + u] = h;
        }
        grid_barrier();
    }
}

// ---------------- NT SGEMM: C[M,N] = A[M,K] * B[N,K]^T + b1[N] (+ b2[N]) ----
// 128x128 tiles, BK=16, 256 threads, 8x8 per thread. M,N %128==0, K %16==0.
__global__ __launch_bounds__(256, 2) void sgemm_nt(
    const float* __restrict__ A, const float* __restrict__ B,
    const float* __restrict__ b1, const float* __restrict__ b2,
    float* __restrict__ C, int M, int N, int K)
{
    __shared__ float As[16][128];
    __shared__ float Bs[16][128];
    const int bm = blockIdx.y * 128;
    const int bn = blockIdx.x * 128;
    const int tid = threadIdx.x;
    const int lr = tid >> 2;          // 0..63
    const int lc = (tid & 3) * 4;     // 0,4,8,12
    const int ty = tid >> 4;          // 0..15
    const int tx = tid & 15;

    float acc[8][8];
#pragma unroll
    for (int i = 0; i < 8; i++)
#pragma unroll
        for (int j = 0; j < 8; j++) acc[i][j] = 0.f;

    for (int k0 = 0; k0 < K; k0 += 16) {
        float4 a0 = *reinterpret_cast<const float4*>(A + (size_t)(bm + lr) * K + k0 + lc);
        float4 a1 = *reinterpret_cast<const float4*>(A + (size_t)(bm + lr + 64) * K + k0 + lc);
        float4 c0 = *reinterpret_cast<const float4*>(B + (size_t)(bn + lr) * K + k0 + lc);
        float4 c1 = *reinterpret_cast<const float4*>(B + (size_t)(bn + lr + 64) * K + k0 + lc);
        __syncthreads();
        As[lc + 0][lr] = a0.x; As[lc + 1][lr] = a0.y; As[lc + 2][lr] = a0.z; As[lc + 3][lr] = a0.w;
        As[lc + 0][lr + 64] = a1.x; As[lc + 1][lr + 64] = a1.y; As[lc + 2][lr + 64] = a1.z; As[lc + 3][lr + 64] = a1.w;
        Bs[lc + 0][lr] = c0.x; Bs[lc + 1][lr] = c0.y; Bs[lc + 2][lr] = c0.z; Bs[lc + 3][lr] = c0.w;
        Bs[lc + 0][lr + 64] = c1.x; Bs[lc + 1][lr + 64] = c1.y; Bs[lc + 2][lr + 64] = c1.z; Bs[lc + 3][lr + 64] = c1.w;
        __syncthreads();
#pragma unroll
        for (int kk = 0; kk < 16; kk++) {
            float4 av0 = *reinterpret_cast<const float4*>(&As[kk][ty * 8]);
            float4 av1 = *reinterpret_cast<const float4*>(&As[kk][ty * 8 + 4]);
            float4 bv0 = *reinterpret_cast<const float4*>(&Bs[kk][tx * 8]);
            float4 bv1 = *reinterpret_cast<const float4*>(&Bs[kk][tx * 8 + 4]);
            float av[8] = {av0.x, av0.y, av0.z, av0.w, av1.x, av1.y, av1.z, av1.w};
            float bv[8] = {bv0.x, bv0.y, bv0.z, bv0.w, bv1.x, bv1.y, bv1.z, bv1.w};
#pragma unroll
            for (int i = 0; i < 8; i++)
#pragma unroll
                for (int j = 0; j < 8; j++)
                    acc[i][j] = fmaf(av[i], bv[j], acc[i][j]);
        }
    }
#pragma unroll
    for (int i = 0; i < 8; i++) {
        int row = bm + ty * 8 + i;
#pragma unroll
        for (int j = 0; j < 8; j++) {
            int col = bn + tx * 8 + j;
            float v = acc[i][j] + b1[col];
            if (b2) v += b2[col];
            C[(size_t)row * N + col] = v;
        }
    }
}

// ---------------- row softmax over OUTDIM=512 -------------------------------
__global__ __launch_bounds__(256) void softmax_rows(float* __restrict__ P)
{
    const int row = blockIdx.x;
    float* q = P + (size_t)row * OUTDIM;
    const int tid = threadIdx.x;
    float v0 = q[tid];
    float v1 = q[tid + 256];
    __shared__ float sm_[8];
    __shared__ float ss_[8];

    float m = fmaxf(v0, v1);
#pragma unroll
    for (int off = 16; off; off >>= 1)
        m = fmaxf(m, __shfl_xor_sync(0xffffffffu, m, off));
    if ((tid & 31) == 0) sm_[tid >> 5] = m;
    __syncthreads();
    if (tid == 0) {
        float t = sm_[0];
#pragma unroll
        for (int i = 1; i < 8; i++) t = fmaxf(t, sm_[i]);
        sm_[0] = t;
    }
    __syncthreads();
    m = sm_[0];

    float e0 = __expf(v0 - m), e1 = __expf(v1 - m);
    float s = e0 + e1;
#pragma unroll
    for (int off = 16; off; off >>= 1)
        s += __shfl_xor_sync(0xffffffffu, s, off);
    if ((tid & 31) == 0) ss_[tid >> 5] = s;
    __syncthreads();
    if (tid == 0) {
        float t = 0.f;
#pragma unroll
        for (int i = 0; i < 8; i++) t += ss_[i];
        ss_[0] = t;
    }
    __syncthreads();
    float inv = 1.0f / ss_[0];
    q[tid] = e0 * inv;
    q[tid + 256] = e1 * inv;
}

// ---------------- launch ----------------------------------------------------
extern "C" void kernel_launch(void* const* d_in, const int* in_sizes, int n_in,
                              void* d_out, int out_size)
{
    (void)in_sizes; (void)n_in; (void)out_size;
    const float* x    = (const float*)d_in[0];
    const float* Wih0 = (const float*)d_in[1];
    const float* Whh0 = (const float*)d_in[2];
    const float* bih0 = (const float*)d_in[3];
    const float* bhh0 = (const float*)d_in[4];
    const float* Wih1 = (const float*)d_in[5];
    const float* Whh1 = (const float*)d_in[6];
    const float* bih1 = (const float*)d_in[7];
    const float* bhh1 = (const float*)d_in[8];
    const float* h0   = (const float*)d_in[9];
    const float* c0   = (const float*)d_in[10];
    const float* fc_w = (const float*)d_in[11];
    const float* fc_b = (const float*)d_in[12];
    float* out = (float*)d_out;

    cudaFuncSetAttribute(lstm_persist, cudaFuncAttributeMaxDynamicSharedMemorySize,
                         (int)sizeof(LstmSmem));

    void* p_g0x = nullptr;
    void* p_h1  = nullptr;
    cudaGetSymbolAddress(&p_g0x, g_g0x);
    cudaGetSymbolAddress(&p_h1,  g_h1all);

    // prologue: g0x = x @ Wih0^T + (bih0 + bhh0)   [4096 x 4096], K=512
    {
        dim3 grid(4 * HDIM / 128, BSEQ / 128);
        sgemm_nt<<<grid, 256>>>(x, Wih0, bih0, bhh0, (float*)p_g0x,
                                BSEQ, 4 * HDIM, INDIM);
    }

    // recurrence
    lstm_persist<<<NCTA, TPB, sizeof(LstmSmem)>>>(Whh0, Wih1, Whh1, bih1, bhh1, h0, c0);

    // epilogue: logits = h1_all @ fc_w^T + fc_b    [4096 x 512], K=1024
    {
        dim3 grid(OUTDIM / 128, BSEQ / 128);
        sgemm_nt<<<grid, 256>>>((const float*)p_h1, fc_w, fc_b, nullptr, out,
                                BSEQ, OUTDIM, HDIM);
    }

    softmax_rows<<<BSEQ, 256>>>(out);
}

// round 13
// speedup vs baseline: 1.0221x; 1.0221x over previous
#include <cuda_runtime.h>
#include <cuda_fp16.h>
#include <cuda_bf16.h>
#include <math.h>

// Problem dims
#define NCTA   128
#define TPB    512
#define HDIM   1024
#define BSEQ   4096
#define INDIM  512
#define OUTDIM 512

// ---------------- scratch (device globals: allocation-free) ----------------
__device__ float g_g0x[(size_t)BSEQ * 4 * HDIM];   // x@Wih0^T + b0  (64 MB)
__device__ float g_h1all[(size_t)BSEQ * HDIM];     // h1 history    (16 MB)
__device__ float g_h0buf[2][HDIM];
__device__ float g_h1buf[2][HDIM];
__device__ unsigned g_bar_count = 0;
__device__ unsigned g_bar_gen = 0;

// ---------------- grid barrier (sense via monotonically increasing gen) ----
__device__ __forceinline__ void grid_barrier() {
    __threadfence();
    __syncthreads();
    if (threadIdx.x == 0) {
        unsigned gen = *(volatile unsigned*)&g_bar_gen;
        if (atomicAdd(&g_bar_count, 1u) == NCTA - 1u) {
            g_bar_count = 0;
            __threadfence();
            *(volatile unsigned*)&g_bar_gen = gen + 1u;
        } else {
            while (*(volatile unsigned*)&g_bar_gen == gen) { }
        }
        __threadfence();
    }
    __syncthreads();
}

// ---------------- persistent LSTM kernel -----------------------------------
struct __align__(16) LstmSmem {
    half  wts[3][32][HDIM];   // [0]=Whh0 rows, [1]=Whh1 rows, [2]=Wih1 rows (192 KB)
    float h0s[HDIM];
    float h1s[HDIM];
    float red[32];            // gate dot results (layer0 in P, layer1 in Q)
    float vpart[32];          // Whh1 @ h1_prev partial
    float b1row[32];          // bih1+bhh1 for owned rows
    float g0s[32];            // prefetched g0x row slice for this step
    float c0s[8];
    float c1s[8];
};

__device__ __forceinline__ void load_frag(const float* __restrict__ hs, int lane,
                                          float hf[32]) {
#pragma unroll
    for (int i = 0; i < 4; i++) {
        float4 a = *reinterpret_cast<const float4*>(hs + i * 256 + lane * 8);
        float4 b = *reinterpret_cast<const float4*>(hs + i * 256 + lane * 8 + 4);
        hf[i * 8 + 0] = a.x; hf[i * 8 + 1] = a.y; hf[i * 8 + 2] = a.z; hf[i * 8 + 3] = a.w;
        hf[i * 8 + 4] = b.x; hf[i * 8 + 5] = b.y; hf[i * 8 + 6] = b.z; hf[i * 8 + 7] = b.w;
    }
}

// dot of one 1024-wide fp16 weight row with the warp's fp32 h fragment
__device__ __forceinline__ float dot_row(const half* __restrict__ wrow,
                                         const float hf[32], int lane) {
    float a0 = 0.f, a1 = 0.f, a2 = 0.f, a3 = 0.f;
#pragma unroll
    for (int i = 0; i < 4; i++) {
        uint4 wv = *reinterpret_cast<const uint4*>(wrow + i * 256 + lane * 8);
        float2 f0 = __half22float2(*reinterpret_cast<const half2*>(&wv.x));
        float2 f1 = __half22float2(*reinterpret_cast<const half2*>(&wv.y));
        float2 f2 = __half22float2(*reinterpret_cast<const half2*>(&wv.z));
        float2 f3 = __half22float2(*reinterpret_cast<const half2*>(&wv.w));
        a0 = fmaf(f0.x, hf[i * 8 + 0], a0); a1 = fmaf(f0.y, hf[i * 8 + 1], a1);
        a2 = fmaf(f1.x, hf[i * 8 + 2], a2); a3 = fmaf(f1.y, hf[i * 8 + 3], a3);
        a0 = fmaf(f2.x, hf[i * 8 + 4], a0); a1 = fmaf(f2.y, hf[i * 8 + 5], a1);
        a2 = fmaf(f3.x, hf[i * 8 + 6], a2); a3 = fmaf(f3.y, hf[i * 8 + 7], a3);
    }
    float acc = (a0 + a1) + (a2 + a3);
#pragma unroll
    for (int off = 16; off; off >>= 1)
        acc += __shfl_xor_sync(0xffffffffu, acc, off);
    return acc;
}

__device__ __forceinline__ float sigm(float x) { return 1.f / (1.f + __expf(-x)); }

__global__ __launch_bounds__(TPB, 1) void lstm_persist(
    const float* __restrict__ Whh0, const float* __restrict__ Wih1,
    const float* __restrict__ Whh1, const float* __restrict__ bih1,
    const float* __restrict__ bhh1, const float* __restrict__ h0in,
    const float* __restrict__ c0in)
{
    extern __shared__ LstmSmem S_[];
    LstmSmem& S = S_[0];
    const int tid   = threadIdx.x;
    const int lane  = tid & 31;
    const int w     = tid >> 5;        // 0..15
    const int b     = blockIdx.x;      // 0..127
    const int jbase = b * 8;           // owned h indices jbase..jbase+7

    // ---- one-time init: weights -> SMEM fp16, biases, cell state, h bufs ----
    for (int idx = tid; idx < 3 * 32 * HDIM; idx += TPB) {
        int m = idx >> 15;             // 0..2
        int r = (idx >> 10) & 31;
        int k = idx & (HDIM - 1);
        int grow = ((r >> 3) << 10) + jbase + (r & 7);
        const float* W = (m == 0) ? Whh0 : (m == 1 ? Whh1 : Wih1);
        S.wts[m][r][k] = __float2half(W[(size_t)grow * HDIM + k]);
    }
    if (tid < 32) {
        int r = tid;
        int grow = ((r >> 3) << 10) + jbase + (r & 7);
        S.b1row[r] = bih1[grow] + bhh1[grow];
        S.g0s[r]   = g_g0x[grow];                 // prefetch step 0
    }
    if (tid < 8) {
        S.c0s[tid] = c0in[jbase + tid];
        S.c1s[tid] = c0in[HDIM + jbase + tid];
    }
    if (b == 0) {
        for (int k = tid; k < HDIM; k += TPB) {
            __stcg(&g_h0buf[1][k], h0in[k]);
            __stcg(&g_h1buf[1][k], h0in[HDIM + k]);
        }
    }
    grid_barrier();

    for (int t = 0; t < BSEQ; ++t) {
        const int rp = (t + 1) & 1;    // read parity  (prev step's h)
        const int wp = t & 1;          // write parity (this step's h)

        // ================= Phase P =================
        // gates0_t = g0x[t] + Whh0 @ h0_prev;  vpart = Whh1 @ h1_prev
        for (int k = tid; k < HDIM; k += TPB) {
            S.h0s[k] = __ldcg(&g_h0buf[rp][k]);
            S.h1s[k] = __ldcg(&g_h1buf[rp][k]);
        }
        __syncthreads();
        if (w < 8) {
            float hf[32];
            load_frag(S.h0s, lane, hf);
#pragma unroll
            for (int q = 0; q < 4; q++) {
                int r = w + 8 * q;
                float d = dot_row(S.wts[0][r], hf, lane);
                if (lane == 0) S.red[r] = S.g0s[r] + d;
            }
        } else {
            float hf[32];
            load_frag(S.h1s, lane, hf);
#pragma unroll
            for (int q = 0; q < 4; q++) {
                int r = (w - 8) + 8 * q;
                float d = dot_row(S.wts[1][r], hf, lane);
                if (lane == 0) S.vpart[r] = d;
            }
        }
        __syncthreads();
        if (tid < 8) {
            int u = tid;
            float gi = S.red[u], gf = S.red[8 + u], gg = S.red[16 + u], go = S.red[24 + u];
            float c = sigm(gf) * S.c0s[u] + sigm(gi) * tanhf(gg);
            S.c0s[u] = c;
            float h = sigm(go) * tanhf(c);
            __stcg(&g_h0buf[wp][jbase + u], h);
        }
        grid_barrier();

        // ================= Phase Q =================
        // gates1_t = Wih1 @ h0n_t + vpart + b1
        for (int k = tid; k < HDIM; k += TPB)
            S.h0s[k] = __ldcg(&g_h0buf[wp][k]);
        __syncthreads();
        {
            float hf[32];
            load_frag(S.h0s, lane, hf);
#pragma unroll
            for (int q = 0; q < 2; q++) {
                int r = w + 16 * q;
                float d = dot_row(S.wts[2][r], hf, lane);
                if (lane == 0) S.red[r] = d + S.vpart[r] + S.b1row[r];
            }
        }
        // prefetch next step's g0x slice (hides DRAM latency off critical path)
        if (tid >= 64 && tid < 96 && t + 1 < BSEQ) {
            int r = tid - 64;
            int grow = ((r >> 3) << 10) + jbase + (r & 7);
            S.g0s[r] = __ldg(&g_g0x[(size_t)(t + 1) * 4 * HDIM + grow]);
        }
        __syncthreads();
        if (tid < 8) {
            int u = tid;
            float gi = S.red[u], gf = S.red[8 + u], gg = S.red[16 + u], go = S.red[24 + u];
            float c = sigm(gf) * S.c1s[u] + sigm(gi) * tanhf(gg);
            S.c1s[u] = c;
            float h = sigm(go) * tanhf(c);
            __stcg(&g_h1buf[wp][jbase + u], h);
            g_h1all[(size_t)t * HDIM + jbase + u] = h;
        }
        grid_barrier();
    }
}

// ---------------- NT SGEMM: C[M,N] = A[M,K] * B[N,K]^T + b1[N] (+ b2[N]) ----
// 128x128 tiles, BK=16, 256 threads, 8x8 per thread. M,N %128==0, K %16==0.
__global__ __launch_bounds__(256, 2) void sgemm_nt(
    const float* __restrict__ A, const float* __restrict__ B,
    const float* __restrict__ b1, const float* __restrict__ b2,
    float* __restrict__ C, int M, int N, int K)
{
    __shared__ float As[16][128];
    __shared__ float Bs[16][128];
    const int bm = blockIdx.y * 128;
    const int bn = blockIdx.x * 128;
    const int tid = threadIdx.x;
    const int lr = tid >> 2;          // 0..63
    const int lc = (tid & 3) * 4;     // 0,4,8,12
    const int ty = tid >> 4;          // 0..15
    const int tx = tid & 15;

    float acc[8][8];
#pragma unroll
    for (int i = 0; i < 8; i++)
#pragma unroll
        for (int j = 0; j < 8; j++) acc[i][j] = 0.f;

    for (int k0 = 0; k0 < K; k0 += 16) {
        float4 a0 = *reinterpret_cast<const float4*>(A + (size_t)(bm + lr) * K + k0 + lc);
        float4 a1 = *reinterpret_cast<const float4*>(A + (size_t)(bm + lr + 64) * K + k0 + lc);
        float4 c0 = *reinterpret_cast<const float4*>(B + (size_t)(bn + lr) * K + k0 + lc);
        float4 c1 = *reinterpret_cast<const float4*>(B + (size_t)(bn + lr + 64) * K + k0 + lc);
        __syncthreads();
        As[lc + 0][lr] = a0.x; As[lc + 1][lr] = a0.y; As[lc + 2][lr] = a0.z; As[lc + 3][lr] = a0.w;
        As[lc + 0][lr + 64] = a1.x; As[lc + 1][lr + 64] = a1.y; As[lc + 2][lr + 64] = a1.z; As[lc + 3][lr + 64] = a1.w;
        Bs[lc + 0][lr] = c0.x; Bs[lc + 1][lr] = c0.y; Bs[lc + 2][lr] = c0.z; Bs[lc + 3][lr] = c0.w;
        Bs[lc + 0][lr + 64] = c1.x; Bs[lc + 1][lr + 64] = c1.y; Bs[lc + 2][lr + 64] = c1.z; Bs[lc + 3][lr + 64] = c1.w;
        __syncthreads();
#pragma unroll
        for (int kk = 0; kk < 16; kk++) {
            float4 av0 = *reinterpret_cast<const float4*>(&As[kk][ty * 8]);
            float4 av1 = *reinterpret_cast<const float4*>(&As[kk][ty * 8 + 4]);
            float4 bv0 = *reinterpret_cast<const float4*>(&Bs[kk][tx * 8]);
            float4 bv1 = *reinterpret_cast<const float4*>(&Bs[kk][tx * 8 + 4]);
            float av[8] = {av0.x, av0.y, av0.z, av0.w, av1.x, av1.y, av1.z, av1.w};
            float bv[8] = {bv0.x, bv0.y, bv0.z, bv0.w, bv1.x, bv1.y, bv1.z, bv1.w};
#pragma unroll
            for (int i = 0; i < 8; i++)
#pragma unroll
                for (int j = 0; j < 8; j++)
                    acc[i][j] = fmaf(av[i], bv[j], acc[i][j]);
        }
    }
#pragma unroll
    for (int i = 0; i < 8; i++) {
        int row = bm + ty * 8 + i;
#pragma unroll
        for (int j = 0; j < 8; j++) {
            int col = bn + tx * 8 + j;
            float v = acc[i][j] + b1[col];
            if (b2) v += b2[col];
            C[(size_t)row * N + col] = v;
        }
    }
}

// ---------------- row softmax over OUTDIM=512 -------------------------------
__global__ __launch_bounds__(256) void softmax_rows(float* __restrict__ P)
{
    const int row = blockIdx.x;
    float* q = P + (size_t)row * OUTDIM;
    const int tid = threadIdx.x;
    float v0 = q[tid];
    float v1 = q[tid + 256];
    __shared__ float sm_[8];
    __shared__ float ss_[8];

    float m = fmaxf(v0, v1);
#pragma unroll
    for (int off = 16; off; off >>= 1)
        m = fmaxf(m, __shfl_xor_sync(0xffffffffu, m, off));
    if ((tid & 31) == 0) sm_[tid >> 5] = m;
    __syncthreads();
    if (tid == 0) {
        float t = sm_[0];
#pragma unroll
        for (int i = 1; i < 8; i++) t = fmaxf(t, sm_[i]);
        sm_[0] = t;
    }
    __syncthreads();
    m = sm_[0];

    float e0 = __expf(v0 - m), e1 = __expf(v1 - m);
    float s = e0 + e1;
#pragma unroll
    for (int off = 16; off; off >>= 1)
        s += __shfl_xor_sync(0xffffffffu, s, off);
    if ((tid & 31) == 0) ss_[tid >> 5] = s;
    __syncthreads();
    if (tid == 0) {
        float t = 0.f;
#pragma unroll
        for (int i = 0; i < 8; i++) t += ss_[i];
        ss_[0] = t;
    }
    __syncthreads();
    float inv = 1.0f / ss_[0];
    q[tid] = e0 * inv;
    q[tid + 256] = e1 * inv;
}

// ---------------- launch ----------------------------------------------------
extern "C" void kernel_launch(void* const* d_in, const int* in_sizes, int n_in,
                              void* d_out, int out_size)
{
    (void)in_sizes; (void)n_in; (void)out_size;
    const float* x    = (const float*)d_in[0];
    const float* Wih0 = (const float*)d_in[1];
    const float* Whh0 = (const float*)d_in[2];
    const float* bih0 = (const float*)d_in[3];
    const float* bhh0 = (const float*)d_in[4];
    const float* Wih1 = (const float*)d_in[5];
    const float* Whh1 = (const float*)d_in[6];
    const float* bih1 = (const float*)d_in[7];
    const float* bhh1 = (const float*)d_in[8];
    const float* h0   = (const float*)d_in[9];
    const float* c0   = (const float*)d_in[10];
    const float* fc_w = (const float*)d_in[11];
    const float* fc_b = (const float*)d_in[12];
    float* out = (float*)d_out;

    cudaFuncSetAttribute(lstm_persist, cudaFuncAttributeMaxDynamicSharedMemorySize,
                         (int)sizeof(LstmSmem));

    void* p_g0x = nullptr;
    void* p_h1  = nullptr;
    cudaGetSymbolAddress(&p_g0x, g_g0x);
    cudaGetSymbolAddress(&p_h1,  g_h1all);

    // prologue: g0x = x @ Wih0^T + (bih0 + bhh0)   [4096 x 4096], K=512
    {
        dim3 grid(4 * HDIM / 128, BSEQ / 128);
        sgemm_nt<<<grid, 256>>>(x, Wih0, bih0, bhh0, (float*)p_g0x,
                                BSEQ, 4 * HDIM, INDIM);
    }

    // recurrence
    lstm_persist<<<NCTA, TPB, sizeof(LstmSmem)>>>(Whh0, Wih1, Whh1, bih1, bhh1, h0, c0);

    // epilogue: logits = h1_all @ fc_w^T + fc_b    [4096 x 512], K=1024
    {
        dim3 grid(OUTDIM / 128, BSEQ / 128);
        sgemm_nt<<<grid, 256>>>((const float*)p_h1, fc_w, fc_b, nullptr, out,
                                BSEQ, OUTDIM, HDIM);
    }

    softmax_rows<<<BSEQ, 256>>>(out);
}

// round 14
// speedup vs baseline: 1.0286x; 1.0064x over previous
#include <cuda_runtime.h>
#include <cuda_fp16.h>
#include <cuda_bf16.h>
#include <math.h>

// Problem dims
#define NCTA   128
#define TPB    512
#define HDIM   1024
#define BSEQ   4096
#define INDIM  512
#define OUTDIM 512

// ---------------- scratch (device globals: allocation-free) ----------------
__device__ float g_g0x[(size_t)BSEQ * 4 * HDIM];   // x@Wih0^T + b0  (64 MB)
__device__ float g_h1all[(size_t)BSEQ * HDIM];     // h1 history    (16 MB)
__device__ float g_h0buf[2][HDIM];
__device__ float g_h1buf[2][HDIM];
__device__ unsigned g_bar_count = 0;
__device__ unsigned g_bar_gen = 0;

// ---------------- grid barrier (sense via monotonically increasing gen) ----
__device__ __forceinline__ void grid_barrier() {
    __threadfence();
    __syncthreads();
    if (threadIdx.x == 0) {
        unsigned gen = *(volatile unsigned*)&g_bar_gen;
        if (atomicAdd(&g_bar_count, 1u) == NCTA - 1u) {
            g_bar_count = 0;
            __threadfence();
            *(volatile unsigned*)&g_bar_gen = gen + 1u;
        } else {
            while (*(volatile unsigned*)&g_bar_gen == gen) { }
        }
        __threadfence();
    }
    __syncthreads();
}

// ---------------- persistent LSTM kernel -----------------------------------
struct __align__(16) LstmSmem {
    half  wts[3][32][HDIM];   // [0]=Whh0 rows, [1]=Whh1 rows, [2]=Wih1 rows (192 KB)
    float h0s[HDIM];
    float h1s[HDIM];
    float red[32];            // gate dot results (layer0 in P, layer1 in Q)
    float vpart[32];          // Whh1 @ h1_prev partial
    float b1row[32];          // bih1+bhh1 for owned rows
    float g0s[32];            // prefetched g0x row slice for this step
    float c0s[8];
    float c1s[8];
};

__device__ __forceinline__ void load_frag(const float* __restrict__ hs, int lane,
                                          float hf[32]) {
#pragma unroll
    for (int i = 0; i < 4; i++) {
        float4 a = *reinterpret_cast<const float4*>(hs + i * 256 + lane * 8);
        float4 b = *reinterpret_cast<const float4*>(hs + i * 256 + lane * 8 + 4);
        hf[i * 8 + 0] = a.x; hf[i * 8 + 1] = a.y; hf[i * 8 + 2] = a.z; hf[i * 8 + 3] = a.w;
        hf[i * 8 + 4] = b.x; hf[i * 8 + 5] = b.y; hf[i * 8 + 6] = b.z; hf[i * 8 + 7] = b.w;
    }
}

// dot of one 1024-wide fp16 weight row with the warp's fp32 h fragment
__device__ __forceinline__ float dot_row(const half* __restrict__ wrow,
                                         const float hf[32], int lane) {
    float a0 = 0.f, a1 = 0.f, a2 = 0.f, a3 = 0.f;
#pragma unroll
    for (int i = 0; i < 4; i++) {
        uint4 wv = *reinterpret_cast<const uint4*>(wrow + i * 256 + lane * 8);
        float2 f0 = __half22float2(*reinterpret_cast<const half2*>(&wv.x));
        float2 f1 = __half22float2(*reinterpret_cast<const half2*>(&wv.y));
        float2 f2 = __half22float2(*reinterpret_cast<const half2*>(&wv.z));
        float2 f3 = __half22float2(*reinterpret_cast<const half2*>(&wv.w));
        a0 = fmaf(f0.x, hf[i * 8 + 0], a0); a1 = fmaf(f0.y, hf[i * 8 + 1], a1);
        a2 = fmaf(f1.x, hf[i * 8 + 2], a2); a3 = fmaf(f1.y, hf[i * 8 + 3], a3);
        a0 = fmaf(f2.x, hf[i * 8 + 4], a0); a1 = fmaf(f2.y, hf[i * 8 + 5], a1);
        a2 = fmaf(f3.x, hf[i * 8 + 6], a2); a3 = fmaf(f3.y, hf[i * 8 + 7], a3);
    }
    float acc = (a0 + a1) + (a2 + a3);
#pragma unroll
    for (int off = 16; off; off >>= 1)
        acc += __shfl_xor_sync(0xffffffffu, acc, off);
    return acc;
}

__device__ __forceinline__ float sigm(float x) { return 1.f / (1.f + __expf(-x)); }

__global__ __launch_bounds__(TPB, 1) void lstm_persist(
    const float* __restrict__ Whh0, const float* __restrict__ Wih1,
    const float* __restrict__ Whh1, const float* __restrict__ bih1,
    const float* __restrict__ bhh1, const float* __restrict__ h0in,
    const float* __restrict__ c0in)
{
    extern __shared__ LstmSmem S_[];
    LstmSmem& S = S_[0];
    const int tid   = threadIdx.x;
    const int lane  = tid & 31;
    const int w     = tid >> 5;        // 0..15
    const int b     = blockIdx.x;      // 0..127
    const int jbase = b * 8;           // owned h indices jbase..jbase+7

    // ---- one-time init: weights -> SMEM fp16, biases, cell state, h bufs ----
    for (int idx = tid; idx < 3 * 32 * HDIM; idx += TPB) {
        int m = idx >> 15;             // 0..2
        int r = (idx >> 10) & 31;
        int k = idx & (HDIM - 1);
        int grow = ((r >> 3) << 10) + jbase + (r & 7);
        const float* W = (m == 0) ? Whh0 : (m == 1 ? Whh1 : Wih1);
        S.wts[m][r][k] = __float2half(W[(size_t)grow * HDIM + k]);
    }
    if (tid < 32) {
        int r = tid;
        int grow = ((r >> 3) << 10) + jbase + (r & 7);
        S.b1row[r] = bih1[grow] + bhh1[grow];
        S.g0s[r]   = g_g0x[grow];                 // prefetch step 0
    }
    if (tid < 8) {
        S.c0s[tid] = c0in[jbase + tid];
        S.c1s[tid] = c0in[HDIM + jbase + tid];
    }
    if (b == 0) {
        for (int k = tid; k < HDIM; k += TPB) {
            __stcg(&g_h0buf[1][k], h0in[k]);
            __stcg(&g_h1buf[1][k], h0in[HDIM + k]);
        }
    }
    grid_barrier();

    for (int t = 0; t < BSEQ; ++t) {
        const int rp = (t + 1) & 1;    // read parity  (prev step's h)
        const int wp = t & 1;          // write parity (this step's h)

        // ================= Phase P =================
        // gates0_t = g0x[t] + Whh0 @ h0_prev;  vpart = Whh1 @ h1_prev
        for (int k = tid; k < HDIM; k += TPB) {
            S.h0s[k] = __ldcg(&g_h0buf[rp][k]);
            S.h1s[k] = __ldcg(&g_h1buf[rp][k]);
        }
        __syncthreads();
        if (w < 8) {
            float hf[32];
            load_frag(S.h0s, lane, hf);
#pragma unroll
            for (int q = 0; q < 4; q++) {
                int r = w + 8 * q;
                float d = dot_row(S.wts[0][r], hf, lane);
                if (lane == 0) S.red[r] = S.g0s[r] + d;
            }
        } else {
            float hf[32];
            load_frag(S.h1s, lane, hf);
#pragma unroll
            for (int q = 0; q < 4; q++) {
                int r = (w - 8) + 8 * q;
                float d = dot_row(S.wts[1][r], hf, lane);
                if (lane == 0) S.vpart[r] = d;
            }
        }
        __syncthreads();
        if (tid < 8) {
            int u = tid;
            float gi = S.red[u], gf = S.red[8 + u], gg = S.red[16 + u], go = S.red[24 + u];
            float c = sigm(gf) * S.c0s[u] + sigm(gi) * tanhf(gg);
            S.c0s[u] = c;
            float h = sigm(go) * tanhf(c);
            __stcg(&g_h0buf[wp][jbase + u], h);
        }
        grid_barrier();

        // ================= Phase Q =================
        // gates1_t = Wih1 @ h0n_t + vpart + b1
        for (int k = tid; k < HDIM; k += TPB)
            S.h0s[k] = __ldcg(&g_h0buf[wp][k]);
        __syncthreads();
        {
            float hf[32];
            load_frag(S.h0s, lane, hf);
#pragma unroll
            for (int q = 0; q < 2; q++) {
                int r = w + 16 * q;
                float d = dot_row(S.wts[2][r], hf, lane);
                if (lane == 0) S.red[r] = d + S.vpart[r] + S.b1row[r];
            }
        }
        // prefetch next step's g0x slice (hides DRAM latency off critical path)
        if (tid >= 64 && tid < 96 && t + 1 < BSEQ) {
            int r = tid - 64;
            int grow = ((r >> 3) << 10) + jbase + (r & 7);
            S.g0s[r] = __ldg(&g_g0x[(size_t)(t + 1) * 4 * HDIM + grow]);
        }
        __syncthreads();
        if (tid < 8) {
            int u = tid;
            float gi = S.red[u], gf = S.red[8 + u], gg = S.red[16 + u], go = S.red[24 + u];
            float c = sigm(gf) * S.c1s[u] + sigm(gi) * tanhf(gg);
            S.c1s[u] = c;
            float h = sigm(go) * tanhf(c);
            __stcg(&g_h1buf[wp][jbase + u], h);
            g_h1all[(size_t)t * HDIM + jbase + u] = h;
        }
        grid_barrier();
    }
}

// ---------------- NT SGEMM: C[M,N] = A[M,K] * B[N,K]^T + b1[N] (+ b2[N]) ----
// 128x128 tiles, BK=16, 256 threads, 8x8 per thread. M,N %128==0, K %16==0.
__global__ __launch_bounds__(256, 2) void sgemm_nt(
    const float* __restrict__ A, const float* __restrict__ B,
    const float* __restrict__ b1, const float* __restrict__ b2,
    float* __restrict__ C, int M, int N, int K)
{
    __shared__ float As[16][128];
    __shared__ float Bs[16][128];
    const int bm = blockIdx.y * 128;
    const int bn = blockIdx.x * 128;
    const int tid = threadIdx.x;
    const int lr = tid >> 2;          // 0..63
    const int lc = (tid & 3) * 4;     // 0,4,8,12
    const int ty = tid >> 4;          // 0..15
    const int tx = tid & 15;

    float acc[8][8];
#pragma unroll
    for (int i = 0; i < 8; i++)
#pragma unroll
        for (int j = 0; j < 8; j++) acc[i][j] = 0.f;

    for (int k0 = 0; k0 < K; k0 += 16) {
        float4 a0 = *reinterpret_cast<const float4*>(A + (size_t)(bm + lr) * K + k0 + lc);
        float4 a1 = *reinterpret_cast<const float4*>(A + (size_t)(bm + lr + 64) * K + k0 + lc);
        float4 c0 = *reinterpret_cast<const float4*>(B + (size_t)(bn + lr) * K + k0 + lc);
        float4 c1 = *reinterpret_cast<const float4*>(B + (size_t)(bn + lr + 64) * K + k0 + lc);
        __syncthreads();
        As[lc + 0][lr] = a0.x; As[lc + 1][lr] = a0.y; As[lc + 2][lr] = a0.z; As[lc + 3][lr] = a0.w;
        As[lc + 0][lr + 64] = a1.x; As[lc + 1][lr + 64] = a1.y; As[lc + 2][lr + 64] = a1.z; As[lc + 3][lr + 64] = a1.w;
        Bs[lc + 0][lr] = c0.x; Bs[lc + 1][lr] = c0.y; Bs[lc + 2][lr] = c0.z; Bs[lc + 3][lr] = c0.w;
        Bs[lc + 0][lr + 64] = c1.x; Bs[lc + 1][lr + 64] = c1.y; Bs[lc + 2][lr + 64] = c1.z; Bs[lc + 3][lr + 64] = c1.w;
        __syncthreads();
#pragma unroll
        for (int kk = 0; kk < 16; kk++) {
            float4 av0 = *reinterpret_cast<const float4*>(&As[kk][ty * 8]);
            float4 av1 = *reinterpret_cast<const float4*>(&As[kk][ty * 8 + 4]);
            float4 bv0 = *reinterpret_cast<const float4*>(&Bs[kk][tx * 8]);
            float4 bv1 = *reinterpret_cast<const float4*>(&Bs[kk][tx * 8 + 4]);
            float av[8] = {av0.x, av0.y, av0.z, av0.w, av1.x, av1.y, av1.z, av1.w};
            float bv[8] = {bv0.x, bv0.y, bv0.z, bv0.w, bv1.x, bv1.y, bv1.z, bv1.w};
#pragma unroll
            for (int i = 0; i < 8; i++)
#pragma unroll
                for (int j = 0; j < 8; j++)
                    acc[i][j] = fmaf(av[i], bv[j], acc[i][j]);
        }
    }
#pragma unroll
    for (int i = 0; i < 8; i++) {
        int row = bm + ty * 8 + i;
#pragma unroll
        for (int j = 0; j < 8; j++) {
            int col = bn + tx * 8 + j;
            float v = acc[i][j] + b1[col];
            if (b2) v += b2[col];
            C[(size_t)row * N + col] = v;
        }
    }
}

// ---------------- row softmax over OUTDIM=512 -------------------------------
__global__ __launch_bounds__(256) void softmax_rows(float* __restrict__ P)
{
    const int row = blockIdx.x;
    float* q = P + (size_t)row * OUTDIM;
    const int tid = threadIdx.x;
    float v0 = q[tid];
    float v1 = q[tid + 256];
    __shared__ float sm_[8];
    __shared__ float ss_[8];

    float m = fmaxf(v0, v1);
#pragma unroll
    for (int off = 16; off; off >>= 1)
        m = fmaxf(m, __shfl_xor_sync(0xffffffffu, m, off));
    if ((tid & 31) == 0) sm_[tid >> 5] = m;
    __syncthreads();
    if (tid == 0) {
        float t = sm_[0];
#pragma unroll
        for (int i = 1; i < 8; i++) t = fmaxf(t, sm_[i]);
        sm_[0] = t;
    }
    __syncthreads();
    m = sm_[0];

    float e0 = __expf(v0 - m), e1 = __expf(v1 - m);
    float s = e0 + e1;
#pragma unroll
    for (int off = 16; off; off >>= 1)
        s += __shfl_xor_sync(0xffffffffu, s, off);
    if ((tid & 31) == 0) ss_[tid >> 5] = s;
    __syncthreads();
    if (tid == 0) {
        float t = 0.f;
#pragma unroll
        for (int i = 0; i < 8; i++) t += ss_[i];
        ss_[0] = t;
    }
    __syncthreads();
    float inv = 1.0f / ss_[0];
    q[tid] = e0 * inv;
    q[tid + 256] = e1 * inv;
}

// ---------------- launch ----------------------------------------------------
extern "C" void kernel_launch(void* const* d_in, const int* in_sizes, int n_in,
                              void* d_out, int out_size)
{
    (void)in_sizes; (void)n_in; (void)out_size;
    const float* x    = (const float*)d_in[0];
    const float* Wih0 = (const float*)d_in[1];
    const float* Whh0 = (const float*)d_in[2];
    const float* bih0 = (const float*)d_in[3];
    const float* bhh0 = (const float*)d_in[4];
    const float* Wih1 = (const float*)d_in[5];
    const float* Whh1 = (const float*)d_in[6];
    const float* bih1 = (const float*)d_in[7];
    const float* bhh1 = (const float*)d_in[8];
    const float* h0   = (const float*)d_in[9];
    const float* c0   = (const float*)d_in[10];
    const float* fc_w = (const float*)d_in[11];
    const float* fc_b = (const float*)d_in[12];
    float* out = (float*)d_out;

    cudaFuncSetAttribute(lstm_persist, cudaFuncAttributeMaxDynamicSharedMemorySize,
                         (int)sizeof(LstmSmem));

    void* p_g0x = nullptr;
    void* p_h1  = nullptr;
    cudaGetSymbolAddress(&p_g0x, g_g0x);
    cudaGetSymbolAddress(&p_h1,  g_h1all);

    // prologue: g0x = x @ Wih0^T + (bih0 + bhh0)   [4096 x 4096], K=512
    {
        dim3 grid(4 * HDIM / 128, BSEQ / 128);
        sgemm_nt<<<grid, 256>>>(x, Wih0, bih0, bhh0, (float*)p_g0x,
                                BSEQ, 4 * HDIM, INDIM);
    }

    // recurrence
    lstm_persist<<<NCTA, TPB, sizeof(LstmSmem)>>>(Whh0, Wih1, Whh1, bih1, bhh1, h0, c0);

    // epilogue: logits = h1_all @ fc_w^T + fc_b    [4096 x 512], K=1024
    {
        dim3 grid(OUTDIM / 128, BSEQ / 128);
        sgemm_nt<<<grid, 256>>>((const float*)p_h1, fc_w, fc_b, nullptr, out,
                                BSEQ, OUTDIM, HDIM);
    }

    softmax_rows<<<BSEQ, 256>>>(out);
}

// round 15
// speedup vs baseline: 1.9703x; 1.9154x over previous
#include <cuda_runtime.h>
#include <cuda_fp16.h>
#include <cuda_bf16.h>
#include <math.h>

// Problem dims
#define NCTA   128
#define TPB    512
#define HDIM   1024
#define BSEQ   4096
#define INDIM  512
#define OUTDIM 512

// ---------------- scratch (device globals: allocation-free) ----------------
__device__ float g_g0x[(size_t)BSEQ * 4 * HDIM];   // x@Wih0^T + b0  (64 MB)
__device__ float g_h1all[(size_t)BSEQ * HDIM];     // h1 history    (16 MB)
__device__ float g_hbuf[2][2 * HDIM];              // packed [h0 | h1], double-buffered
__device__ unsigned g_bar_count;

// ---------------- fence-free grid barrier (monotonic count, acq/rel) -------
__device__ __forceinline__ void grid_barrier(unsigned target) {
    __syncthreads();   // CTA-local writes happen-before thread 0's release
    if (threadIdx.x == 0) {
        unsigned long long ga;
        asm("cvta.to.global.u64 %0, %1;" : "=l"(ga) : "l"(&g_bar_count));
        asm volatile("red.release.gpu.global.add.u32 [%0], 1;" :: "l"(ga) : "memory");
        unsigned v;
        do {
            asm volatile("ld.acquire.gpu.global.u32 %0, [%1];" : "=r"(v) : "l"(ga) : "memory");
        } while (v < target);
    }
    __syncthreads();
}

__global__ void reset_bar() { g_bar_count = 0; }

// ---------------- persistent LSTM kernel -----------------------------------
// Per CTA: owns 8 h-units (jbase..jbase+7). Holds 96 fp16 weight rows in SMEM:
//   rows  0..31 : Whh0  (layer0 recurrent)      -> uses h0 frag
//   rows 32..63 : Wih1  (layer1 input)          -> uses h0 frag
//   rows 64..95 : Whh1  (layer1 recurrent)      -> uses h1 frag
// Pipelined: iteration t computes layer0 step t AND layer1 step t-1 together.
struct __align__(16) LstmSmem {
    half  wts[96][HDIM];     // 192 KB
    float h[2 * HDIM];       // 8 KB: [0..1023]=h0n(t-1), [1024..2047]=h1n(t-2)
    float red[96];
    float b1row[32];
    float g0s[32];           // g0x row slice for current step t
    float c0s[8];
    float c1s[8];
};

__device__ __forceinline__ void load_frag(const float* __restrict__ hs, int lane,
                                          float hf[32]) {
#pragma unroll
    for (int i = 0; i < 4; i++) {
        float4 a = *reinterpret_cast<const float4*>(hs + i * 256 + lane * 8);
        float4 b = *reinterpret_cast<const float4*>(hs + i * 256 + lane * 8 + 4);
        hf[i * 8 + 0] = a.x; hf[i * 8 + 1] = a.y; hf[i * 8 + 2] = a.z; hf[i * 8 + 3] = a.w;
        hf[i * 8 + 4] = b.x; hf[i * 8 + 5] = b.y; hf[i * 8 + 6] = b.z; hf[i * 8 + 7] = b.w;
    }
}

__device__ __forceinline__ float dot_row(const half* __restrict__ wrow,
                                         const float hf[32], int lane) {
    float a0 = 0.f, a1 = 0.f, a2 = 0.f, a3 = 0.f;
#pragma unroll
    for (int i = 0; i < 4; i++) {
        uint4 wv = *reinterpret_cast<const uint4*>(wrow + i * 256 + lane * 8);
        float2 f0 = __half22float2(*reinterpret_cast<const half2*>(&wv.x));
        float2 f1 = __half22float2(*reinterpret_cast<const half2*>(&wv.y));
        float2 f2 = __half22float2(*reinterpret_cast<const half2*>(&wv.z));
        float2 f3 = __half22float2(*reinterpret_cast<const half2*>(&wv.w));
        a0 = fmaf(f0.x, hf[i * 8 + 0], a0); a1 = fmaf(f0.y, hf[i * 8 + 1], a1);
        a2 = fmaf(f1.x, hf[i * 8 + 2], a2); a3 = fmaf(f1.y, hf[i * 8 + 3], a3);
        a0 = fmaf(f2.x, hf[i * 8 + 4], a0); a1 = fmaf(f2.y, hf[i * 8 + 5], a1);
        a2 = fmaf(f3.x, hf[i * 8 + 6], a2); a3 = fmaf(f3.y, hf[i * 8 + 7], a3);
    }
    float acc = (a0 + a1) + (a2 + a3);
#pragma unroll
    for (int off = 16; off; off >>= 1)
        acc += __shfl_xor_sync(0xffffffffu, acc, off);
    return acc;
}

__device__ __forceinline__ float sigm(float x) { return 1.f / (1.f + __expf(-x)); }

__global__ __launch_bounds__(TPB, 1) void lstm_persist(
    const float* __restrict__ Whh0, const float* __restrict__ Wih1,
    const float* __restrict__ Whh1, const float* __restrict__ bih1,
    const float* __restrict__ bhh1, const float* __restrict__ h0in,
    const float* __restrict__ c0in)
{
    extern __shared__ LstmSmem S_[];
    LstmSmem& S = S_[0];
    const int tid   = threadIdx.x;
    const int lane  = tid & 31;
    const int w     = tid >> 5;        // 0..15
    const int b     = blockIdx.x;      // 0..127
    const int jbase = b * 8;

    // ---- one-time init ----
    for (int idx = tid; idx < 96 * HDIM; idx += TPB) {
        int r = idx >> 10;
        int k = idx & (HDIM - 1);
        int m = r >> 5;                // 0=Whh0, 1=Wih1, 2=Whh1
        int rr = r & 31;
        int grow = ((rr >> 3) << 10) + jbase + (rr & 7);
        const float* W = (m == 0) ? Whh0 : ((m == 1) ? Wih1 : Whh1);
        S.wts[r][k] = __float2half(W[(size_t)grow * HDIM + k]);
    }
    if (tid < 32) {
        int grow = ((tid >> 3) << 10) + jbase + (tid & 7);
        S.b1row[tid] = bih1[grow] + bhh1[grow];
        S.g0s[tid]   = g_g0x[grow];            // step-0 slice (includes b0)
    }
    if (tid < 8) {
        S.c0s[tid] = c0in[jbase + tid];
        S.c1s[tid] = c0in[HDIM + tid + jbase];
    }
    if (b == 0) {
        for (int k = tid; k < 2 * HDIM; k += TPB) {
            float v = h0in[k];                 // [0..1023]=h0 init, [1024..2047]=h1 init
            __stcg(&g_hbuf[0][k], v);
            __stcg(&g_hbuf[1][k], v);          // h1 part of buf1 needed at iter 1
        }
    }
    const int myrow = ((tid >> 3) << 10) + jbase + (tid & 7);   // tid<32 g0 prefetch row
    grid_barrier(NCTA);

    // ---- pipelined recurrence: iter t does layer0(t) and layer1(t-1) ----
    for (int t = 0; t <= BSEQ; ++t) {
        const int rb = t & 1, wb = rb ^ 1;

        // broadcast read: packed [h0n(t-1) | h1n(t-2)], one float4 per thread
        float4 hv = __ldcg(reinterpret_cast<const float4*>(&g_hbuf[rb][tid * 4]));
        // prefetch next step's g0x slice (off critical path)
        float gpre = 0.f;
        if (tid < 32 && t + 1 < BSEQ)
            gpre = __ldcg(&g_g0x[(size_t)(t + 1) * (4 * HDIM) + myrow]);
        *reinterpret_cast<float4*>(&S.h[tid * 4]) = hv;
        __syncthreads();

        float hf[32];
        load_frag((w < 12) ? S.h : (S.h + HDIM), lane, hf);
        if (w < 8) {
            // Whh0: 4 rows each, add g0x (already includes both layer-0 biases)
#pragma unroll
            for (int q = 0; q < 4; q++) {
                int r = w * 4 + q;
                float d = dot_row(S.wts[r], hf, lane);
                if (lane == 0) S.red[r] = d + S.g0s[r];
            }
        } else {
            // Wih1 (warps 8-11) / Whh1 (warps 12-15): 8 rows each
            int base = (w < 12) ? (32 + (w - 8) * 8) : (64 + (w - 12) * 8);
            for (int q = 0; q < 8; q++) {
                float d = dot_row(S.wts[base + q], hf, lane);
                if (lane == 0) S.red[base + q] = d;
            }
        }
        __syncthreads();

        if (tid < 8) {
            if (t < BSEQ) {            // layer0 step t
                int u = tid;
                float gi = S.red[u], gf = S.red[8 + u], gg = S.red[16 + u], go = S.red[24 + u];
                float c = sigm(gf) * S.c0s[u] + sigm(gi) * tanhf(gg);
                S.c0s[u] = c;
                float h = sigm(go) * tanhf(c);
                __stcg(&g_hbuf[wb][jbase + u], h);
            }
        } else if (tid < 16) {
            if (t >= 1) {              // layer1 step t-1
                int u = tid - 8;
                float gi = S.red[32 + u]      + S.red[64 + u]      + S.b1row[u];
                float gf = S.red[32 + 8 + u]  + S.red[64 + 8 + u]  + S.b1row[8 + u];
                float gg = S.red[32 + 16 + u] + S.red[64 + 16 + u] + S.b1row[16 + u];
                float go = S.red[32 + 24 + u] + S.red[64 + 24 + u] + S.b1row[24 + u];
                float c = sigm(gf) * S.c1s[u] + sigm(gi) * tanhf(gg);
                S.c1s[u] = c;
                float h = sigm(go) * tanhf(c);
                __stcg(&g_hbuf[wb][HDIM + jbase + u], h);
                g_h1all[(size_t)(t - 1) * HDIM + jbase + u] = h;
            }
        }
        if (tid < 32 && t + 1 < BSEQ) S.g0s[tid] = gpre;   // consumed after next sync

        grid_barrier((unsigned)NCTA * (unsigned)(t + 2));
    }
}

// ---------------- NT SGEMM: C[M,N] = A[M,K] * B[N,K]^T + b1[N] (+ b2[N]) ----
__global__ __launch_bounds__(256, 2) void sgemm_nt(
    const float* __restrict__ A, const float* __restrict__ B,
    const float* __restrict__ b1, const float* __restrict__ b2,
    float* __restrict__ C, int M, int N, int K)
{
    __shared__ float As[16][128];
    __shared__ float Bs[16][128];
    const int bm = blockIdx.y * 128;
    const int bn = blockIdx.x * 128;
    const int tid = threadIdx.x;
    const int lr = tid >> 2;
    const int lc = (tid & 3) * 4;
    const int ty = tid >> 4;
    const int tx = tid & 15;

    float acc[8][8];
#pragma unroll
    for (int i = 0; i < 8; i++)
#pragma unroll
        for (int j = 0; j < 8; j++) acc[i][j] = 0.f;

    for (int k0 = 0; k0 < K; k0 += 16) {
        float4 a0 = *reinterpret_cast<const float4*>(A + (size_t)(bm + lr) * K + k0 + lc);
        float4 a1 = *reinterpret_cast<const float4*>(A + (size_t)(bm + lr + 64) * K + k0 + lc);
        float4 c0 = *reinterpret_cast<const float4*>(B + (size_t)(bn + lr) * K + k0 + lc);
        float4 c1 = *reinterpret_cast<const float4*>(B + (size_t)(bn + lr + 64) * K + k0 + lc);
        __syncthreads();
        As[lc + 0][lr] = a0.x; As[lc + 1][lr] = a0.y; As[lc + 2][lr] = a0.z; As[lc + 3][lr] = a0.w;
        As[lc + 0][lr + 64] = a1.x; As[lc + 1][lr + 64] = a1.y; As[lc + 2][lr + 64] = a1.z; As[lc + 3][lr + 64] = a1.w;
        Bs[lc + 0][lr] = c0.x; Bs[lc + 1][lr] = c0.y; Bs[lc + 2][lr] = c0.z; Bs[lc + 3][lr] = c0.w;
        Bs[lc + 0][lr + 64] = c1.x; Bs[lc + 1][lr + 64] = c1.y; Bs[lc + 2][lr + 64] = c1.z; Bs[lc + 3][lr + 64] = c1.w;
        __syncthreads();
#pragma unroll
        for (int kk = 0; kk < 16; kk++) {
            float4 av0 = *reinterpret_cast<const float4*>(&As[kk][ty * 8]);
            float4 av1 = *reinterpret_cast<const float4*>(&As[kk][ty * 8 + 4]);
            float4 bv0 = *reinterpret_cast<const float4*>(&Bs[kk][tx * 8]);
            float4 bv1 = *reinterpret_cast<const float4*>(&Bs[kk][tx * 8 + 4]);
            float av[8] = {av0.x, av0.y, av0.z, av0.w, av1.x, av1.y, av1.z, av1.w};
            float bv[8] = {bv0.x, bv0.y, bv0.z, bv0.w, bv1.x, bv1.y, bv1.z, bv1.w};
#pragma unroll
            for (int i = 0; i < 8; i++)
#pragma unroll
                for (int j = 0; j < 8; j++)
                    acc[i][j] = fmaf(av[i], bv[j], acc[i][j]);
        }
    }
#pragma unroll
    for (int i = 0; i < 8; i++) {
        int row = bm + ty * 8 + i;
#pragma unroll
        for (int j = 0; j < 8; j++) {
            int col = bn + tx * 8 + j;
            float v = acc[i][j] + b1[col];
            if (b2) v += b2[col];
            C[(size_t)row * N + col] = v;
        }
    }
}

// ---------------- row softmax over OUTDIM=512 -------------------------------
__global__ __launch_bounds__(256) void softmax_rows(float* __restrict__ P)
{
    const int row = blockIdx.x;
    float* q = P + (size_t)row * OUTDIM;
    const int tid = threadIdx.x;
    float v0 = q[tid];
    float v1 = q[tid + 256];
    __shared__ float sm_[8];
    __shared__ float ss_[8];

    float m = fmaxf(v0, v1);
#pragma unroll
    for (int off = 16; off; off >>= 1)
        m = fmaxf(m, __shfl_xor_sync(0xffffffffu, m, off));
    if ((tid & 31) == 0) sm_[tid >> 5] = m;
    __syncthreads();
    if (tid == 0) {
        float t = sm_[0];
#pragma unroll
        for (int i = 1; i < 8; i++) t = fmaxf(t, sm_[i]);
        sm_[0] = t;
    }
    __syncthreads();
    m = sm_[0];

    float e0 = __expf(v0 - m), e1 = __expf(v1 - m);
    float s = e0 + e1;
#pragma unroll
    for (int off = 16; off; off >>= 1)
        s += __shfl_xor_sync(0xffffffffu, s, off);
    if ((tid & 31) == 0) ss_[tid >> 5] = s;
    __syncthreads();
    if (tid == 0) {
        float t = 0.f;
#pragma unroll
        for (int i = 0; i < 8; i++) t += ss_[i];
        ss_[0] = t;
    }
    __syncthreads();
    float inv = 1.0f / ss_[0];
    q[tid] = e0 * inv;
    q[tid + 256] = e1 * inv;
}

// ---------------- launch ----------------------------------------------------
extern "C" void kernel_launch(void* const* d_in, const int* in_sizes, int n_in,
                              void* d_out, int out_size)
{
    (void)in_sizes; (void)n_in; (void)out_size;
    const float* x    = (const float*)d_in[0];
    const float* Wih0 = (const float*)d_in[1];
    const float* Whh0 = (const float*)d_in[2];
    const float* bih0 = (const float*)d_in[3];
    const float* bhh0 = (const float*)d_in[4];
    const float* Wih1 = (const float*)d_in[5];
    const float* Whh1 = (const float*)d_in[6];
    const float* bih1 = (const float*)d_in[7];
    const float* bhh1 = (const float*)d_in[8];
    const float* h0   = (const float*)d_in[9];
    const float* c0   = (const float*)d_in[10];
    const float* fc_w = (const float*)d_in[11];
    const float* fc_b = (const float*)d_in[12];
    float* out = (float*)d_out;

    cudaFuncSetAttribute(lstm_persist, cudaFuncAttributeMaxDynamicSharedMemorySize,
                         (int)sizeof(LstmSmem));

    void* p_g0x = nullptr;
    void* p_h1  = nullptr;
    cudaGetSymbolAddress(&p_g0x, g_g0x);
    cudaGetSymbolAddress(&p_h1,  g_h1all);

    // reset barrier counter (stream-ordered before the persistent kernel)
    reset_bar<<<1, 1>>>();

    // prologue: g0x = x @ Wih0^T + (bih0 + bhh0)   [4096 x 4096], K=512
    {
        dim3 grid(4 * HDIM / 128, BSEQ / 128);
        sgemm_nt<<<grid, 256>>>(x, Wih0, bih0, bhh0, (float*)p_g0x,
                                BSEQ, 4 * HDIM, INDIM);
    }

    // recurrence (one barrier per step, layer1 pipelined one step behind)
    lstm_persist<<<NCTA, TPB, sizeof(LstmSmem)>>>(Whh0, Wih1, Whh1, bih1, bhh1, h0, c0);

    // epilogue: logits = h1_all @ fc_w^T + fc_b    [4096 x 512], K=1024
    {
        dim3 grid(OUTDIM / 128, BSEQ / 128);
        sgemm_nt<<<grid, 256>>>((const float*)p_h1, fc_w, fc_b, nullptr, out,
                                BSEQ, OUTDIM, HDIM);
    }

    softmax_rows<<<BSEQ, 256>>>(out);
}